// round 2
// baseline (speedup 1.0000x reference)
#include <cuda_runtime.h>
#include <cuda_bf16.h>

#define KN 32
#define DF 128

__global__ void __launch_bounds__(256)
coatt_kernel(const float* __restrict__ feat,
             const int* __restrict__ sim_idx,
             const int* __restrict__ cor_idx,
             float* __restrict__ out)
{
    // Transposed tiles: [d][k], pad to 33 for conflict-free column access
    __shared__ float sDt[DF][KN + 1];
    __shared__ float sQt[DF][KN + 1];
    __shared__ float sL[KN][KN + 1];           // raw logits
    __shared__ float sCinv[KN], sMc[KN];       // column stats (AS softmax)
    __shared__ float sRs[KN],   sMr[KN];       // row stats (AC softmax)
    __shared__ float sw[KN], sp[KN], sv[KN];
    __shared__ int   sIdxD[KN], sIdxQ[KN];
    __shared__ float sm[3 * DF];

    const int n   = blockIdx.x;
    const int tid = threadIdx.x;

    // ---- load neighbor indices ----
    if (tid < KN)            sIdxD[tid]      = sim_idx[n * KN + tid];
    else if (tid < 2 * KN)   sIdxQ[tid - KN] = cor_idx[n * KN + (tid - KN)];
    __syncthreads();

    // ---- gather Dm, Qm into transposed smem ----
    {
        const int j = tid >> 3;
        const int c = tid & 7;
        const float4* rowD = (const float4*)(feat + (size_t)sIdxD[j] * DF);
        const float4* rowQ = (const float4*)(feat + (size_t)sIdxQ[j] * DF);
        #pragma unroll
        for (int it = 0; it < 4; it++) {
            int c4 = c + 8 * it;
            float4 vD = __ldg(rowD + c4);
            float4 vQ = __ldg(rowQ + c4);
            int d0 = 4 * c4;
            sDt[d0 + 0][j] = vD.x; sDt[d0 + 1][j] = vD.y;
            sDt[d0 + 2][j] = vD.z; sDt[d0 + 3][j] = vD.w;
            sQt[d0 + 0][j] = vQ.x; sQt[d0 + 1][j] = vQ.y;
            sQt[d0 + 2][j] = vQ.z; sQt[d0 + 3][j] = vQ.w;
        }
    }
    __syncthreads();

    // ---- L = Dm @ Qm^T, 2x2 register tile per thread ----
    const int ty = tid >> 4, tx = tid & 15;
    const int k0 = 2 * ty, k1 = k0 + 1;
    const int j0 = 2 * tx, j1 = j0 + 1;
    float a00 = 0.f, a01 = 0.f, a10 = 0.f, a11 = 0.f;
    #pragma unroll 8
    for (int d = 0; d < DF; d++) {
        float x0 = sDt[d][k0], x1 = sDt[d][k1];
        float y0 = sQt[d][j0], y1 = sQt[d][j1];
        a00 += x0 * y0; a01 += x0 * y1;
        a10 += x1 * y0; a11 += x1 * y1;
    }
    sL[k0][j0] = a00; sL[k0][j1] = a01;
    sL[k1][j0] = a10; sL[k1][j1] = a11;
    __syncthreads();

    // ---- per-column stats (AS softmax, stabilized per column) on warp 0
    // ---- per-row stats (AC softmax, stabilized per row) on warp 1, parallel
    if (tid < 32) {
        const int j = tid;
        float mc = -1e30f;
        #pragma unroll
        for (int k = 0; k < KN; k++) mc = fmaxf(mc, sL[k][j]);
        float cs = 0.f;
        #pragma unroll
        for (int k = 0; k < KN; k++) cs += __expf(sL[k][j] - mc);
        sMc[j]   = mc;
        sCinv[j] = 1.0f / (32.0f * cs);
    } else if (tid < 64) {
        const int k = tid - 32;
        float mr = -1e30f;
        #pragma unroll
        for (int j = 0; j < KN; j++) mr = fmaxf(mr, sL[k][j]);
        float rs = 0.f;
        #pragma unroll
        for (int j = 0; j < KN; j++) rs += __expf(sL[k][j] - mr);
        sMr[k] = mr;
        sRs[k] = rs;
    }
    __syncthreads();

    // ---- w[j] = sum_k exp(L[j,k]-Mc[k]) / (32 c_k)    (mean_k of AS, applied to Dm/CQ)
    if (tid < 32) {
        const int j = tid;
        float wj = 0.f;
        #pragma unroll
        for (int k = 0; k < KN; k++)
            wj += __expf(sL[j][k] - sMc[k]) * sCinv[k];
        sw[j] = wj;
        sp[j] = wj / sRs[j];
    }
    __syncthreads();

    // ---- v[j] = sum_k p[k] * exp(L[k,j]-Mr[k])        (= AC^T p)
    if (tid < 32) {
        const int j = tid;
        float vj = 0.f;
        #pragma unroll
        for (int k = 0; k < KN; k++)
            vj += sp[k] * __expf(sL[k][j] - sMr[k]);
        sv[j] = vj;
    }
    __syncthreads();

    // ---- m vectors: m = [mean_k Qm | w^T Dm | v^T Qm], length 384 ----
    if (tid < DF) {
        const int d = tid;
        float m1 = 0.f, m2 = 0.f, m3 = 0.f;
        #pragma unroll
        for (int j = 0; j < KN; j++) {
            float q  = sQt[d][j];
            float dd = sDt[d][j];
            m1 += q;
            m2 += sw[j] * dd;
            m3 += sv[j] * q;
        }
        sm[d]          = m1 * (1.0f / 32.0f);
        sm[DF + d]     = m2;
        sm[2 * DF + d] = m3;
    }
    __syncthreads();

    // ---- AvgPool1d(3,3) over the 384-vector, add residual ----
    if (tid < DF) {
        const int g = tid;
        float h = (sm[3 * g] + sm[3 * g + 1] + sm[3 * g + 2]) * (1.0f / 3.0f);
        out[(size_t)n * DF + g] = feat[(size_t)n * DF + g] + h;
    }
}

extern "C" void kernel_launch(void* const* d_in, const int* in_sizes, int n_in,
                              void* d_out, int out_size)
{
    const float* feat = (const float*)d_in[0];
    const int*   sim  = (const int*)d_in[1];
    const int*   cor  = (const int*)d_in[2];
    float*       out  = (float*)d_out;

    const int n_nodes = in_sizes[1] / KN;   // 20000
    coatt_kernel<<<n_nodes, 256>>>(feat, sim, cor, out);
}